// round 14
// baseline (speedup 1.0000x reference)
#include <cuda_runtime.h>
#include <cuda_bf16.h>
#include <cstdint>

#define D 128
#define P 8
#define NMAX 100000
#define EMAX 1620000
#define LMAX 3
#define BS2 130   // Bs stride (words): ≡2 mod 8 -> float2 frag loads conflict-free

// Scratch (device globals — no allocation allowed)
__device__ float          g_ax[(size_t)NMAX * D];          // SpMM out (tf32-prerounded fp32)
__device__ __nv_bfloat16  g_xbf[(size_t)NMAX * D];         // x converted to bf16
__device__ __nv_bfloat16  g_hA[(size_t)NMAX * D];          // ping (bf16)
__device__ __nv_bfloat16  g_hB[(size_t)NMAX * D];          // pong (bf16)
__device__ int            g_row_ptr[NMAX + 1];
__device__ float          g_wwT[LMAX * D * D];             // [l][k][o]
__device__ int2           g_ev[EMAX];                      // {col byte-offset, val bits}

// ---------------------------------------------------------------------------
__global__ void build_row_ptr_k(const int* __restrict__ edge_row, int E, int N) {
    int r = blockIdx.x * blockDim.x + threadIdx.x;
    if (r > N) return;
    int lo = 0, hi = E;
    while (lo < hi) {
        int mid = (lo + hi) >> 1;
        if (edge_row[mid] < r) lo = mid + 1; else hi = mid;
    }
    g_row_ptr[r] = lo;
}

// ---------------------------------------------------------------------------
// Pack (col, val) -> {col * 256 bytes, val bits}. One-time prep.
// ---------------------------------------------------------------------------
__global__ void pack_edges_k(const int* __restrict__ col, const float* __restrict__ val,
                             int E) {
    int i = blockIdx.x * blockDim.x + threadIdx.x;
    if (i >= E) return;
    int2 e;
    e.x = __ldg(col + i) << 8;          // byte offset of bf16 row (128 * 2B)
    e.y = __float_as_int(__ldg(val + i));
    g_ev[i] = e;
}

// ---------------------------------------------------------------------------
__global__ void build_weights_k(const float* __restrict__ sp, const float* __restrict__ lw) {
    int l = blockIdx.x >> 7;
    int i = blockIdx.x & 127;
    int o = threadIdx.x;

    float w[P];
    float m = -1e30f;
#pragma unroll
    for (int p = 0; p < P; p++) { w[p] = lw[l * P + p]; m = fmaxf(m, w[p]); }
    float s = 0.f;
#pragma unroll
    for (int p = 0; p < P; p++) { w[p] = expf(w[p] - m); s += w[p]; }
    float inv = 1.f / s;

    const float* base = sp + (((size_t)l * D + o) * D + i) * P;
    float acc = 0.f;
#pragma unroll
    for (int p = 0; p < P; p++) acc = fmaf(base[p], w[p] * inv, acc);
    g_wwT[((size_t)l * D + i) * D + o] = acc;
}

// ---------------------------------------------------------------------------
__global__ void cvt_x_k(const float* __restrict__ x, int total4) {
    int i = blockIdx.x * blockDim.x + threadIdx.x;
    if (i >= total4) return;
    float4 v = __ldg(((const float4*)x) + i);
    __nv_bfloat162 a = __floats2bfloat162_rn(v.x, v.y);
    __nv_bfloat162 b = __floats2bfloat162_rn(v.z, v.w);
    ((__nv_bfloat162*)g_xbf)[2 * i]     = a;
    ((__nv_bfloat162*)g_xbf)[2 * i + 1] = b;
}

// ---------------------------------------------------------------------------
__device__ __forceinline__ uint32_t cvt_tf32(float x) {
    uint32_t r;
    asm("cvt.rn.tf32.f32 %0, %1;" : "=r"(r) : "f"(x));
    return r;
}

// ---------------------------------------------------------------------------
// SpMM over bf16 features: one warp per row, 2-edge unroll, packed edges,
// fp32 accumulate, tf32-prerounded row-major output.
// ---------------------------------------------------------------------------
__global__ void spmm_k(const __nv_bfloat16* __restrict__ h, int N) {
    int warp = (int)((blockIdx.x * blockDim.x + threadIdx.x) >> 5);
    int lane = threadIdx.x & 31;
    if (warp >= N) return;
    int s = g_row_ptr[warp];
    int e = g_row_ptr[warp + 1];
    const char* hb = (const char*)h + lane * 8;   // lane's 8-byte slot within a row
    float4 acc0 = make_float4(0.f, 0.f, 0.f, 0.f);
    float4 acc1 = make_float4(0.f, 0.f, 0.f, 0.f);
    int k = s;
    for (; k + 1 < e; k += 2) {
        int2 e0 = __ldg(g_ev + k);
        int2 e1 = __ldg(g_ev + k + 1);
        float v0 = __int_as_float(e0.y);
        float v1 = __int_as_float(e1.y);
        uint2 u0 = __ldg((const uint2*)(hb + e0.x));
        uint2 u1 = __ldg((const uint2*)(hb + e1.x));
        acc0.x = fmaf(v0, __uint_as_float(u0.x << 16),         acc0.x);
        acc0.y = fmaf(v0, __uint_as_float(u0.x & 0xffff0000u), acc0.y);
        acc0.z = fmaf(v0, __uint_as_float(u0.y << 16),         acc0.z);
        acc0.w = fmaf(v0, __uint_as_float(u0.y & 0xffff0000u), acc0.w);
        acc1.x = fmaf(v1, __uint_as_float(u1.x << 16),         acc1.x);
        acc1.y = fmaf(v1, __uint_as_float(u1.x & 0xffff0000u), acc1.y);
        acc1.z = fmaf(v1, __uint_as_float(u1.y << 16),         acc1.z);
        acc1.w = fmaf(v1, __uint_as_float(u1.y & 0xffff0000u), acc1.w);
    }
    if (k < e) {
        int2 e0 = __ldg(g_ev + k);
        float v0 = __int_as_float(e0.y);
        uint2 u0 = __ldg((const uint2*)(hb + e0.x));
        acc0.x = fmaf(v0, __uint_as_float(u0.x << 16),         acc0.x);
        acc0.y = fmaf(v0, __uint_as_float(u0.x & 0xffff0000u), acc0.y);
        acc0.z = fmaf(v0, __uint_as_float(u0.y << 16),         acc0.z);
        acc0.w = fmaf(v0, __uint_as_float(u0.y & 0xffff0000u), acc0.w);
    }
    acc0.x += acc1.x; acc0.y += acc1.y; acc0.z += acc1.z; acc0.w += acc1.w;

    // pre-round to tf32 (RN) so the GEMM A path needs no cvt
    float4 st;
    st.x = __uint_as_float(cvt_tf32(acc0.x));
    st.y = __uint_as_float(cvt_tf32(acc0.y));
    st.z = __uint_as_float(cvt_tf32(acc0.z));
    st.w = __uint_as_float(cvt_tf32(acc0.w));
    ((float4*)(g_ax + (size_t)warp * D))[lane] = st;
}

// ---------------------------------------------------------------------------
__device__ __forceinline__ void mma_tf32(float (&d)[4],
                                         uint32_t a0, uint32_t a1, uint32_t a2, uint32_t a3,
                                         uint32_t b0, uint32_t b1) {
    asm volatile(
        "mma.sync.aligned.m16n8k8.row.col.f32.tf32.tf32.f32 "
        "{%0,%1,%2,%3},{%4,%5,%6,%7},{%8,%9},{%0,%1,%2,%3};"
        : "+f"(d[0]), "+f"(d[1]), "+f"(d[2]), "+f"(d[3])
        : "r"(a0), "r"(a1), "r"(a2), "r"(a3), "r"(b0), "r"(b1));
}

// ---------------------------------------------------------------------------
// Tensor-core GEMM (1xTF32, RN): block = 128 rows x 128 cols, 256 threads,
// warp 32x64, 2 blocks/SM. A is already tf32-rounded (raw bit reinterpret).
// B tf32 k-permuted j-contiguous in smem. RELU layers emit bf16; final fp32.
// ---------------------------------------------------------------------------
template <bool RELU>
__global__ __launch_bounds__(256, 2) void gemm_tc(const float* __restrict__ A,
                                                  const float* __restrict__ B,
                                                  void* __restrict__ Cv, int N) {
    extern __shared__ float Bs[];   // [128][BS2], logical rows k-permuted

    const int tid = threadIdx.x;

    // stage B (128 x 128): permute k-rows, swap (j,g) within 64-halves, cvt tf32
#pragma unroll
    for (int i = tid; i < 128 * 32; i += 256) {
        int p  = i >> 5;
        int c4 = (i & 31) << 2;
        int pk = p & 15;
        int lpk = (pk >> 2) + ((pk & 1) << 2) + ((pk & 2) << 2);
        int lrow = (p & ~15) | lpk;
        float4 v = __ldg((const float4*)(B + p * 128 + c4));
        float vv[4] = {v.x, v.y, v.z, v.w};
#pragma unroll
        for (int e = 0; e < 4; e++) {
            int o = c4 + e;
            int hh = o >> 6;
            int j  = (o >> 3) & 7;
            int g  = o & 7;
            Bs[lrow * BS2 + (hh << 6) + (g << 3) + j] =
                __uint_as_float(cvt_tf32(vv[e]));
        }
    }
    __syncthreads();

    const int warp = tid >> 5;
    const int lane = tid & 31;
    const int g  = lane >> 2;
    const int t  = lane & 3;
    const int wr = warp >> 1;
    const int wc = warp & 1;

    const int row0 = blockIdx.x * 128 + wr * 32;

    int  r[4] = {row0 + g, row0 + g + 8, row0 + g + 16, row0 + g + 24};
    bool ok[4];
    const float* pA[4];
#pragma unroll
    for (int q = 0; q < 4; q++) {
        ok[q] = r[q] < N;
        pA[q] = A + (size_t)r[q] * D + 4 * t;
    }

    float acc[2][8][4];
#pragma unroll
    for (int s = 0; s < 2; s++)
#pragma unroll
        for (int j = 0; j < 8; j++)
#pragma unroll
            for (int q = 0; q < 4; q++) acc[s][j][q] = 0.f;

    const int bbase = wc * 64 + g * 8;

#pragma unroll
    for (int kb = 0; kb < 8; kb++) {
        float4 v[4];
#pragma unroll
        for (int q = 0; q < 4; q++)
            v[q] = ok[q] ? __ldg((const float4*)(pA[q] + kb * 16))
                         : make_float4(0.f, 0.f, 0.f, 0.f);

#pragma unroll
        for (int c = 0; c < 2; c++) {
            // A values are pre-rounded tf32: raw bit reinterpret, no cvt
            uint32_t a0[2], a1[2], a2[2], a3[2];
#pragma unroll
            for (int s = 0; s < 2; s++) {
                a0[s] = __float_as_uint((c == 0) ? v[2*s].x   : v[2*s].z);
                a2[s] = __float_as_uint((c == 0) ? v[2*s].y   : v[2*s].w);
                a1[s] = __float_as_uint((c == 0) ? v[2*s+1].x : v[2*s+1].z);
                a3[s] = __float_as_uint((c == 0) ? v[2*s+1].y : v[2*s+1].w);
            }

            const int kk = kb * 16 + c * 8;
            const float* brow0 = &Bs[(kk + t) * BS2 + bbase];
            const float* brow1 = &Bs[(kk + t + 4) * BS2 + bbase];
            uint2 b0p[4], b1p[4];
#pragma unroll
            for (int m = 0; m < 4; m++) {
                b0p[m] = *(const uint2*)(brow0 + 2 * m);
                b1p[m] = *(const uint2*)(brow1 + 2 * m);
            }

#pragma unroll
            for (int j = 0; j < 8; j++) {
                uint32_t b0 = (j & 1) ? b0p[j >> 1].y : b0p[j >> 1].x;
                uint32_t b1 = (j & 1) ? b1p[j >> 1].y : b1p[j >> 1].x;
#pragma unroll
                for (int s = 0; s < 2; s++)
                    mma_tf32(acc[s][j], a0[s], a1[s], a2[s], a3[s], b0, b1);
            }
        }
    }

    // epilogue
#pragma unroll
    for (int s = 0; s < 2; s++) {
        int rA = row0 + g + 16 * s;
        int rB = rA + 8;
        bool okA = rA < N;
        bool okB = rB < N;
#pragma unroll
        for (int j = 0; j < 8; j++) {
            float v0 = acc[s][j][0], v1 = acc[s][j][1];
            float v2 = acc[s][j][2], v3 = acc[s][j][3];
            int c = wc * 64 + j * 8 + 2 * t;
            if (RELU) {
                v0 = fmaxf(v0, 0.f); v1 = fmaxf(v1, 0.f);
                v2 = fmaxf(v2, 0.f); v3 = fmaxf(v3, 0.f);
                __nv_bfloat16* C = (__nv_bfloat16*)Cv;
                __nv_bfloat162 pA2 = __floats2bfloat162_rn(v0, v1);
                __nv_bfloat162 pB2 = __floats2bfloat162_rn(v2, v3);
                if (okA) *(__nv_bfloat162*)(C + (size_t)rA * D + c) = pA2;
                if (okB) *(__nv_bfloat162*)(C + (size_t)rB * D + c) = pB2;
            } else {
                float* C = (float*)Cv;
                if (okA) *(float2*)(C + (size_t)rA * D + c) = make_float2(v0, v1);
                if (okB) *(float2*)(C + (size_t)rB * D + c) = make_float2(v2, v3);
            }
        }
    }
}

// ---------------------------------------------------------------------------
extern "C" void kernel_launch(void* const* d_in, const int* in_sizes, int n_in,
                              void* d_out, int out_size) {
    const int*   edge_row  = (const int*)d_in[0];
    const int*   edge_col  = (const int*)d_in[1];
    const float* edge_vals = (const float*)d_in[2];
    const float* x         = (const float*)d_in[3];
    const float* sp        = (const float*)d_in[4];
    const float* lw        = (const float*)d_in[5];

    const int E = in_sizes[0];
    const int N = in_sizes[3] / D;
    const int L = in_sizes[5] / P;

    void *p_ax, *p_xbf, *p_hA, *p_hB, *p_ww;
    cudaGetSymbolAddress(&p_ax, g_ax);
    cudaGetSymbolAddress(&p_xbf, g_xbf);
    cudaGetSymbolAddress(&p_hA, g_hA);
    cudaGetSymbolAddress(&p_hB, g_hB);
    cudaGetSymbolAddress(&p_ww, g_wwT);

    const int smem_bytes = 128 * BS2 * 4;   // 66560
    cudaFuncSetAttribute(gemm_tc<true>,  cudaFuncAttributeMaxDynamicSharedMemorySize, smem_bytes);
    cudaFuncSetAttribute(gemm_tc<false>, cudaFuncAttributeMaxDynamicSharedMemorySize, smem_bytes);

    build_row_ptr_k<<<(N + 256) / 256, 256>>>(edge_row, E, N);
    pack_edges_k<<<(E + 255) / 256, 256>>>(edge_col, edge_vals, E);
    build_weights_k<<<L * D, D>>>(sp, lw);
    const int total4 = N * D / 4;
    cvt_x_k<<<(total4 + 255) / 256, 256>>>(x, total4);

    __nv_bfloat16* bufs[2] = {(__nv_bfloat16*)p_hA, (__nv_bfloat16*)p_hB};
    const __nv_bfloat16* hin = (const __nv_bfloat16*)p_xbf;
    const int gemm_blocks = (N + 127) / 128;
    const int spmm_blocks = (N + 7) / 8;

    for (int l = 0; l < L; l++) {
        spmm_k<<<spmm_blocks, 256>>>(hin, N);
        const float* Bm = (const float*)p_ww + (size_t)l * D * D;
        if (l < L - 1) {
            gemm_tc<true><<<gemm_blocks, 256, smem_bytes>>>((const float*)p_ax, Bm,
                                                            (void*)bufs[l & 1], N);
            hin = bufs[l & 1];
        } else {
            gemm_tc<false><<<gemm_blocks, 256, smem_bytes>>>((const float*)p_ax, Bm,
                                                             d_out, N);
        }
    }
}

// round 16
// speedup vs baseline: 1.0814x; 1.0814x over previous
#include <cuda_runtime.h>
#include <cuda_bf16.h>
#include <cstdint>

#define D 128
#define P 8
#define NMAX 100000
#define LMAX 3
#define BS2 130   // Bs stride (words): ≡2 mod 8 -> float2 frag loads conflict-free

// Scratch (device globals — no allocation allowed)
__device__ float          g_ax[(size_t)NMAX * D];          // SpMM out (tf32-prerounded fp32)
__device__ __nv_bfloat16  g_hA[(size_t)NMAX * D];          // ping (bf16)
__device__ __nv_bfloat16  g_hB[(size_t)NMAX * D];          // pong (bf16)
__device__ int            g_row_ptr[NMAX + 1];
__device__ float          g_wwP[LMAX * 128 * BS2];         // B pre-permuted smem image, tf32

// ---------------------------------------------------------------------------
__global__ void build_row_ptr_k(const int* __restrict__ edge_row, int E, int N) {
    int r = blockIdx.x * blockDim.x + threadIdx.x;
    if (r > N) return;
    int lo = 0, hi = E;
    while (lo < hi) {
        int mid = (lo + hi) >> 1;
        if (edge_row[mid] < r) lo = mid + 1; else hi = mid;
    }
    g_row_ptr[r] = lo;
}

// ---------------------------------------------------------------------------
__device__ __forceinline__ uint32_t cvt_tf32(float x) {
    uint32_t r;
    asm("cvt.rn.tf32.f32 %0, %1;" : "=r"(r) : "f"(x));
    return r;
}

// ---------------------------------------------------------------------------
// Effective weight, written directly in the GEMM's smem image layout:
// row = k-permuted (within 16-groups), col = (hh<<6)+(g<<3)+j, stride BS2,
// values tf32-RN-rounded. blockIdx = l*128 + k, thread = o.
// ---------------------------------------------------------------------------
__global__ void build_weights_k(const float* __restrict__ sp, const float* __restrict__ lw) {
    int l = blockIdx.x >> 7;
    int i = blockIdx.x & 127;   // physical k
    int o = threadIdx.x;        // output col

    float w[P];
    float m = -1e30f;
#pragma unroll
    for (int p = 0; p < P; p++) { w[p] = lw[l * P + p]; m = fmaxf(m, w[p]); }
    float s = 0.f;
#pragma unroll
    for (int p = 0; p < P; p++) { w[p] = expf(w[p] - m); s += w[p]; }
    float inv = 1.f / s;

    const float* base = sp + (((size_t)l * D + o) * D + i) * P;
    float acc = 0.f;
#pragma unroll
    for (int p = 0; p < P; p++) acc = fmaf(base[p], w[p] * inv, acc);

    // k-row permutation within 16-group
    int pk  = i & 15;
    int lpk = (pk >> 2) + ((pk & 1) << 2) + ((pk & 2) << 2);
    int lrow = (i & ~15) | lpk;
    // column shuffle: j-contiguous within 64-halves
    int col = ((o >> 6) << 6) + ((o & 7) << 3) + ((o >> 3) & 7);
    g_wwP[(size_t)l * 128 * BS2 + lrow * BS2 + col] = __uint_as_float(cvt_tf32(acc));
}

// ---------------------------------------------------------------------------
// SpMM layer 0: gather fp32 x directly (no pre-conversion). One warp per row,
// 2-edge unroll, tf32-prerounded output.
// ---------------------------------------------------------------------------
__global__ void spmm_f32_k(const int* __restrict__ col, const float* __restrict__ val,
                           const float* __restrict__ h, int N) {
    int warp = (int)((blockIdx.x * blockDim.x + threadIdx.x) >> 5);
    int lane = threadIdx.x & 31;
    if (warp >= N) return;
    int s = g_row_ptr[warp];
    int e = g_row_ptr[warp + 1];
    float4 acc0 = make_float4(0.f, 0.f, 0.f, 0.f);
    float4 acc1 = make_float4(0.f, 0.f, 0.f, 0.f);
    int k = s;
    for (; k + 1 < e; k += 2) {
        int   c0 = __ldg(col + k);
        int   c1 = __ldg(col + k + 1);
        float v0 = __ldg(val + k);
        float v1 = __ldg(val + k + 1);
        float4 h0 = __ldg(((const float4*)(h + (size_t)c0 * D)) + lane);
        float4 h1 = __ldg(((const float4*)(h + (size_t)c1 * D)) + lane);
        acc0.x = fmaf(v0, h0.x, acc0.x); acc0.y = fmaf(v0, h0.y, acc0.y);
        acc0.z = fmaf(v0, h0.z, acc0.z); acc0.w = fmaf(v0, h0.w, acc0.w);
        acc1.x = fmaf(v1, h1.x, acc1.x); acc1.y = fmaf(v1, h1.y, acc1.y);
        acc1.z = fmaf(v1, h1.z, acc1.z); acc1.w = fmaf(v1, h1.w, acc1.w);
    }
    if (k < e) {
        int   c0 = __ldg(col + k);
        float v0 = __ldg(val + k);
        float4 h0 = __ldg(((const float4*)(h + (size_t)c0 * D)) + lane);
        acc0.x = fmaf(v0, h0.x, acc0.x); acc0.y = fmaf(v0, h0.y, acc0.y);
        acc0.z = fmaf(v0, h0.z, acc0.z); acc0.w = fmaf(v0, h0.w, acc0.w);
    }
    acc0.x += acc1.x; acc0.y += acc1.y; acc0.z += acc1.z; acc0.w += acc1.w;

    float4 st;
    st.x = __uint_as_float(cvt_tf32(acc0.x));
    st.y = __uint_as_float(cvt_tf32(acc0.y));
    st.z = __uint_as_float(cvt_tf32(acc0.z));
    st.w = __uint_as_float(cvt_tf32(acc0.w));
    ((float4*)(g_ax + (size_t)warp * D))[lane] = st;
}

// ---------------------------------------------------------------------------
// SpMM layers 1+: gather bf16 h. One warp per row, 2-edge unroll,
// fp32 accumulate, tf32-prerounded output. (R10-proven loop.)
// ---------------------------------------------------------------------------
__global__ void spmm_bf16_k(const int* __restrict__ col, const float* __restrict__ val,
                            const __nv_bfloat16* __restrict__ h, int N) {
    int warp = (int)((blockIdx.x * blockDim.x + threadIdx.x) >> 5);
    int lane = threadIdx.x & 31;
    if (warp >= N) return;
    int s = g_row_ptr[warp];
    int e = g_row_ptr[warp + 1];
    float4 acc0 = make_float4(0.f, 0.f, 0.f, 0.f);
    float4 acc1 = make_float4(0.f, 0.f, 0.f, 0.f);
    int k = s;
    for (; k + 1 < e; k += 2) {
        int   c0 = __ldg(col + k);
        int   c1 = __ldg(col + k + 1);
        float v0 = __ldg(val + k);
        float v1 = __ldg(val + k + 1);
        uint2 u0 = __ldg((const uint2*)(h + (size_t)c0 * D) + lane);
        uint2 u1 = __ldg((const uint2*)(h + (size_t)c1 * D) + lane);
        acc0.x = fmaf(v0, __uint_as_float(u0.x << 16),         acc0.x);
        acc0.y = fmaf(v0, __uint_as_float(u0.x & 0xffff0000u), acc0.y);
        acc0.z = fmaf(v0, __uint_as_float(u0.y << 16),         acc0.z);
        acc0.w = fmaf(v0, __uint_as_float(u0.y & 0xffff0000u), acc0.w);
        acc1.x = fmaf(v1, __uint_as_float(u1.x << 16),         acc1.x);
        acc1.y = fmaf(v1, __uint_as_float(u1.x & 0xffff0000u), acc1.y);
        acc1.z = fmaf(v1, __uint_as_float(u1.y << 16),         acc1.z);
        acc1.w = fmaf(v1, __uint_as_float(u1.y & 0xffff0000u), acc1.w);
    }
    if (k < e) {
        int   c0 = __ldg(col + k);
        float v0 = __ldg(val + k);
        uint2 u0 = __ldg((const uint2*)(h + (size_t)c0 * D) + lane);
        acc0.x = fmaf(v0, __uint_as_float(u0.x << 16),         acc0.x);
        acc0.y = fmaf(v0, __uint_as_float(u0.x & 0xffff0000u), acc0.y);
        acc0.z = fmaf(v0, __uint_as_float(u0.y << 16),         acc0.z);
        acc0.w = fmaf(v0, __uint_as_float(u0.y & 0xffff0000u), acc0.w);
    }
    acc0.x += acc1.x; acc0.y += acc1.y; acc0.z += acc1.z; acc0.w += acc1.w;

    float4 st;
    st.x = __uint_as_float(cvt_tf32(acc0.x));
    st.y = __uint_as_float(cvt_tf32(acc0.y));
    st.z = __uint_as_float(cvt_tf32(acc0.z));
    st.w = __uint_as_float(cvt_tf32(acc0.w));
    ((float4*)(g_ax + (size_t)warp * D))[lane] = st;
}

// ---------------------------------------------------------------------------
__device__ __forceinline__ void mma_tf32(float (&d)[4],
                                         uint32_t a0, uint32_t a1, uint32_t a2, uint32_t a3,
                                         uint32_t b0, uint32_t b1) {
    asm volatile(
        "mma.sync.aligned.m16n8k8.row.col.f32.tf32.tf32.f32 "
        "{%0,%1,%2,%3},{%4,%5,%6,%7},{%8,%9},{%0,%1,%2,%3};"
        : "+f"(d[0]), "+f"(d[1]), "+f"(d[2]), "+f"(d[3])
        : "r"(a0), "r"(a1), "r"(a2), "r"(a3), "r"(b0), "r"(b1));
}

// ---------------------------------------------------------------------------
// Tensor-core GEMM (1xTF32, RN): block = 128 rows x 128 cols, 256 threads,
// warp 32x64, 2 blocks/SM. A is tf32-prerounded (raw reinterpret). B comes
// pre-permuted+pre-rounded from g_wwP -> staging is a straight float4 copy.
// RELU layers emit bf16; final layer emits fp32.
// ---------------------------------------------------------------------------
template <bool RELU>
__global__ __launch_bounds__(256, 2) void gemm_tc(const float* __restrict__ A,
                                                  const float* __restrict__ Bp,
                                                  void* __restrict__ Cv, int N) {
    extern __shared__ float Bs[];   // [128][BS2] image, copied verbatim

    const int tid = threadIdx.x;

    // stage B: verbatim vectorized copy of the 128*BS2-float image
#pragma unroll
    for (int i = tid; i < (128 * BS2) / 4; i += 256) {
        ((float4*)Bs)[i] = __ldg(((const float4*)Bp) + i);
    }
    __syncthreads();

    const int warp = tid >> 5;
    const int lane = tid & 31;
    const int g  = lane >> 2;
    const int t  = lane & 3;
    const int wr = warp >> 1;
    const int wc = warp & 1;

    const int row0 = blockIdx.x * 128 + wr * 32;

    int  r[4] = {row0 + g, row0 + g + 8, row0 + g + 16, row0 + g + 24};
    bool ok[4];
    const float* pA[4];
#pragma unroll
    for (int q = 0; q < 4; q++) {
        ok[q] = r[q] < N;
        pA[q] = A + (size_t)r[q] * D + 4 * t;
    }

    float acc[2][8][4];
#pragma unroll
    for (int s = 0; s < 2; s++)
#pragma unroll
        for (int j = 0; j < 8; j++)
#pragma unroll
            for (int q = 0; q < 4; q++) acc[s][j][q] = 0.f;

    const int bbase = wc * 64 + g * 8;

#pragma unroll
    for (int kb = 0; kb < 8; kb++) {
        float4 v[4];
#pragma unroll
        for (int q = 0; q < 4; q++)
            v[q] = ok[q] ? __ldg((const float4*)(pA[q] + kb * 16))
                         : make_float4(0.f, 0.f, 0.f, 0.f);

#pragma unroll
        for (int c = 0; c < 2; c++) {
            // A pre-rounded tf32: raw bit reinterpret
            uint32_t a0[2], a1[2], a2[2], a3[2];
#pragma unroll
            for (int s = 0; s < 2; s++) {
                a0[s] = __float_as_uint((c == 0) ? v[2*s].x   : v[2*s].z);
                a2[s] = __float_as_uint((c == 0) ? v[2*s].y   : v[2*s].w);
                a1[s] = __float_as_uint((c == 0) ? v[2*s+1].x : v[2*s+1].z);
                a3[s] = __float_as_uint((c == 0) ? v[2*s+1].y : v[2*s+1].w);
            }

            const int kk = kb * 16 + c * 8;
            const float* brow0 = &Bs[(kk + t) * BS2 + bbase];
            const float* brow1 = &Bs[(kk + t + 4) * BS2 + bbase];
            uint2 b0p[4], b1p[4];
#pragma unroll
            for (int m = 0; m < 4; m++) {
                b0p[m] = *(const uint2*)(brow0 + 2 * m);
                b1p[m] = *(const uint2*)(brow1 + 2 * m);
            }

#pragma unroll
            for (int j = 0; j < 8; j++) {
                uint32_t b0 = (j & 1) ? b0p[j >> 1].y : b0p[j >> 1].x;
                uint32_t b1 = (j & 1) ? b1p[j >> 1].y : b1p[j >> 1].x;
#pragma unroll
                for (int s = 0; s < 2; s++)
                    mma_tf32(acc[s][j], a0[s], a1[s], a2[s], a3[s], b0, b1);
            }
        }
    }

    // epilogue
#pragma unroll
    for (int s = 0; s < 2; s++) {
        int rA = row0 + g + 16 * s;
        int rB = rA + 8;
        bool okA = rA < N;
        bool okB = rB < N;
#pragma unroll
        for (int j = 0; j < 8; j++) {
            float v0 = acc[s][j][0], v1 = acc[s][j][1];
            float v2 = acc[s][j][2], v3 = acc[s][j][3];
            int c = wc * 64 + j * 8 + 2 * t;
            if (RELU) {
                v0 = fmaxf(v0, 0.f); v1 = fmaxf(v1, 0.f);
                v2 = fmaxf(v2, 0.f); v3 = fmaxf(v3, 0.f);
                __nv_bfloat16* C = (__nv_bfloat16*)Cv;
                __nv_bfloat162 pA2 = __floats2bfloat162_rn(v0, v1);
                __nv_bfloat162 pB2 = __floats2bfloat162_rn(v2, v3);
                if (okA) *(__nv_bfloat162*)(C + (size_t)rA * D + c) = pA2;
                if (okB) *(__nv_bfloat162*)(C + (size_t)rB * D + c) = pB2;
            } else {
                float* C = (float*)Cv;
                if (okA) *(float2*)(C + (size_t)rA * D + c) = make_float2(v0, v1);
                if (okB) *(float2*)(C + (size_t)rB * D + c) = make_float2(v2, v3);
            }
        }
    }
}

// ---------------------------------------------------------------------------
extern "C" void kernel_launch(void* const* d_in, const int* in_sizes, int n_in,
                              void* d_out, int out_size) {
    const int*   edge_row  = (const int*)d_in[0];
    const int*   edge_col  = (const int*)d_in[1];
    const float* edge_vals = (const float*)d_in[2];
    const float* x         = (const float*)d_in[3];
    const float* sp        = (const float*)d_in[4];
    const float* lw        = (const float*)d_in[5];

    const int E = in_sizes[0];
    const int N = in_sizes[3] / D;
    const int L = in_sizes[5] / P;

    void *p_ax, *p_hA, *p_hB, *p_ww;
    cudaGetSymbolAddress(&p_ax, g_ax);
    cudaGetSymbolAddress(&p_hA, g_hA);
    cudaGetSymbolAddress(&p_hB, g_hB);
    cudaGetSymbolAddress(&p_ww, g_wwP);

    const int smem_bytes = 128 * BS2 * 4;   // 66560
    cudaFuncSetAttribute(gemm_tc<true>,  cudaFuncAttributeMaxDynamicSharedMemorySize, smem_bytes);
    cudaFuncSetAttribute(gemm_tc<false>, cudaFuncAttributeMaxDynamicSharedMemorySize, smem_bytes);

    build_row_ptr_k<<<(N + 256) / 256, 256>>>(edge_row, E, N);
    build_weights_k<<<L * D, D>>>(sp, lw);

    __nv_bfloat16* bufs[2] = {(__nv_bfloat16*)p_hA, (__nv_bfloat16*)p_hB};
    const int gemm_blocks = (N + 127) / 128;
    const int spmm_blocks = (N + 7) / 8;

    for (int l = 0; l < L; l++) {
        if (l == 0)
            spmm_f32_k<<<spmm_blocks, 256>>>(edge_col, edge_vals, x, N);
        else
            spmm_bf16_k<<<spmm_blocks, 256>>>(edge_col, edge_vals, bufs[(l - 1) & 1], N);

        const float* Bm = (const float*)p_ww + (size_t)l * 128 * BS2;
        if (l < L - 1)
            gemm_tc<true><<<gemm_blocks, 256, smem_bytes>>>((const float*)p_ax, Bm,
                                                            (void*)bufs[l & 1], N);
        else
            gemm_tc<false><<<gemm_blocks, 256, smem_bytes>>>((const float*)p_ax, Bm,
                                                             d_out, N);
    }
}